// round 9
// baseline (speedup 1.0000x reference)
#include <cuda_runtime.h>
#include <cuda_bf16.h>
#include <math.h>
#include <stdint.h>

// Problem constants (GAT_1090921693772)
#define NN 65536
#define EE 1310720
#define ET (NN + EE)          // edges + self loops
#define INF_ 768
#define HIDF 128
#define HEADS 8
#define C1 16
#define OUTF 2
#define NEG_SLOPE 0.2f
#define EPS 1e-16f

// ---------------- scratch (static device globals; no allocation) -------------
__device__ __align__(16) int   g_deg[NN];
__device__ __align__(16) int   g_off[NN + 1];
__device__ __align__(16) int   g_cur[NN];
__device__ __align__(16) int   g_csr[ET];
__device__ __align__(16) int   g_bsum[64];
__device__ __align__(16) int   g_boff[64];
__device__ __align__(16) float g_h1[(size_t)NN * HIDF];
__device__ __align__(16) float g_proj[(size_t)NN * HIDF];
__device__ __align__(16) float g_as1[NN * HEADS];
__device__ __align__(16) float g_ad1[NN * HEADS];
__device__ __align__(16) float g_hmid[(size_t)NN * HIDF];
__device__ __align__(16) float g_h2[NN * OUTF];
__device__ __align__(16) float g_as2[NN];
__device__ __align__(16) float g_ad2[NN];
__device__ int g_is64;   // 1 if edge_index is int64, 0 if int32

// bf16 hi/lo split of concatenated weights [256 n][768 k] (n<128 = W1, n>=128 = Wp)
__device__ __align__(16) __nv_bfloat16 g_wc_hi[256 * 768];
__device__ __align__(16) __nv_bfloat16 g_wc_lo[256 * 768];

// ---------------- PTX helpers (baseline ISA only — no tcgen05) ---------------
__device__ __forceinline__ uint32_t smem_u32(const void* p) {
    uint32_t a;
    asm("{ .reg .u64 t; cvta.to.shared.u64 t, %1; cvt.u32.u64 %0, t; }" : "=r"(a) : "l"(p));
    return a;
}
__device__ __forceinline__ void ldsm4(uint32_t* r, uint32_t addr) {
    asm volatile("ldmatrix.sync.aligned.m8n8.x4.shared.b16 {%0,%1,%2,%3}, [%4];"
                 : "=r"(r[0]), "=r"(r[1]), "=r"(r[2]), "=r"(r[3]) : "r"(addr));
}
__device__ __forceinline__ void mma_bf16(float* c, const uint32_t* a, const uint32_t* b) {
    asm volatile(
        "mma.sync.aligned.m16n8k16.row.col.f32.bf16.bf16.f32 "
        "{%0,%1,%2,%3}, {%4,%5,%6,%7}, {%8,%9}, {%0,%1,%2,%3};"
        : "+f"(c[0]), "+f"(c[1]), "+f"(c[2]), "+f"(c[3])
        : "r"(a[0]), "r"(a[1]), "r"(a[2]), "r"(a[3]), "r"(b[0]), "r"(b[1]));
}
__device__ __forceinline__ void cp16(uint32_t dst, const void* src) {
    asm volatile("cp.async.cg.shared.global [%0], [%1], 16;" :: "r"(dst), "l"(src));
}
__device__ __forceinline__ void cp_commit() {
    asm volatile("cp.async.commit_group;" ::: "memory");
}
__device__ __forceinline__ void cp_wait1() {
    asm volatile("cp.async.wait_group 1;" ::: "memory");
}
__device__ __forceinline__ void cp_wait0() {
    asm volatile("cp.async.wait_group 0;" ::: "memory");
}

// ---------------- weight prep: split W1||Wp into bf16 hi/lo [256][768] -------
__global__ void k_wprep(const float* __restrict__ W1, const float* __restrict__ Wp) {
    int idx = blockIdx.x * 256 + threadIdx.x;
    if (idx >= 256 * 768) return;
    int n = idx / 768, k = idx % 768;
    float v = (n < 128) ? W1[k * HIDF + n] : Wp[k * HIDF + (n - 128)];
    __nv_bfloat16 hi = __float2bfloat16(v);
    float lo = v - __bfloat162float(hi);
    g_wc_hi[idx] = hi;
    g_wc_lo[idx] = __float2bfloat16(lo);
}

// ---------------- tensor-core GEMM via mma.sync (bf16 3-product split) -------
// CTA tile 128 rows x 256 cols (cols 0-127 -> g_h1, 128-255 -> g_proj).
// 8 warps in 2x4 grid of 64x64 warp tiles. BK=32, K=768 -> 24 chunks.
// A staged via regs (next chunk loaded during MMA), B double-buffered cp.async.
#define SAPAD 40   // bf16 row stride: 80B = 16B-aligned, conflict-free ldmatrix
// dynamic smem layout (bytes):
//   Ahi @ 0       (128*40*2 = 10240)
//   Alo @ 10240
//   B buf0 hi @ 20480 (256*40*2 = 20480), buf0 lo @ 40960
//   B buf1 hi @ 61440,                    buf1 lo @ 81920
#define GEMM_SMEM 102400
__global__ __launch_bounds__(256) void k_gemm_mma(const float* __restrict__ x) {
    extern __shared__ __align__(16) char dsm[];
    uint32_t usm = smem_u32(dsm);
    const uint32_t uAhi = usm, uAlo = usm + 10240;

    int tid = threadIdx.x;
    int wid = tid >> 5, lane = tid & 31;
    int warp_m = wid >> 2, warp_n = wid & 3;     // 2 x 4 warp grid (64x64 tiles)
    long long rowBase = (long long)blockIdx.x * 128;

    float acc[4][8][4];
#pragma unroll
    for (int i = 0; i < 4; i++)
#pragma unroll
        for (int j = 0; j < 8; j++)
#pragma unroll
            for (int q = 0; q < 4; q++) acc[i][j][q] = 0.f;

    // ldmatrix lane addressing
    int ar = (lane & 7) + ((lane >> 3) & 1) * 8;
    int akg = ((lane >> 4) & 1) * 8;
    int br = (lane & 7) + ((lane >> 4) & 1) * 8;
    int bkg = ((lane >> 3) & 1) * 8;

    int r_ld = tid >> 1;                 // A row this thread loads (0..127)
    int kh = (tid & 1) * 16;             // A k-half

    // B cp.async: thread t copies row t (64B hi + 64B lo per chunk)
    const char* wh_base = (const char*)(g_wc_hi + (size_t)tid * INF_);
    const char* wl_base = (const char*)(g_wc_lo + (size_t)tid * INF_);
    uint32_t bdst_h = usm + 20480 + tid * 80;
    uint32_t bdst_l = usm + 40960 + tid * 80;

    float4 rA[4];
    // prologue: B chunk 0 -> buf0; A chunk 0 -> regs
    {
#pragma unroll
        for (int q = 0; q < 4; q++) {
            cp16(bdst_h + q * 16, wh_base + q * 16);
            cp16(bdst_l + q * 16, wl_base + q * 16);
        }
        cp_commit();
        const float* xp = x + (rowBase + r_ld) * INF_ + kh;
#pragma unroll
        for (int q = 0; q < 4; q++) rA[q] = *(const float4*)(xp + q * 4);
    }

    for (int c = 0; c < 24; c++) {
        __syncthreads();   // prior MMA done reading A smem and B buf (c+1)&1
        // ---- convert staged A regs -> smem hi/lo ----
        {
            __nv_bfloat16* dh = (__nv_bfloat16*)(dsm) + r_ld * SAPAD + kh;
            __nv_bfloat16* dl = (__nv_bfloat16*)(dsm + 10240) + r_ld * SAPAD + kh;
#pragma unroll
            for (int q = 0; q < 4; q++) {
                float4 v = rA[q];
                __nv_bfloat16 h0 = __float2bfloat16(v.x);
                __nv_bfloat16 h1 = __float2bfloat16(v.y);
                __nv_bfloat16 h2 = __float2bfloat16(v.z);
                __nv_bfloat16 h3 = __float2bfloat16(v.w);
                __nv_bfloat162 ph0; ph0.x = h0; ph0.y = h1;
                __nv_bfloat162 ph1; ph1.x = h2; ph1.y = h3;
                __nv_bfloat162 pl0 = __floats2bfloat162_rn(v.x - __bfloat162float(h0),
                                                           v.y - __bfloat162float(h1));
                __nv_bfloat162 pl1 = __floats2bfloat162_rn(v.z - __bfloat162float(h2),
                                                           v.w - __bfloat162float(h3));
                *(__nv_bfloat162*)(dh + q * 4)     = ph0;
                *(__nv_bfloat162*)(dh + q * 4 + 2) = ph1;
                *(__nv_bfloat162*)(dl + q * 4)     = pl0;
                *(__nv_bfloat162*)(dl + q * 4 + 2) = pl1;
            }
        }
        // ---- prefetch next chunk: B via cp.async (other buffer), A via regs ----
        if (c + 1 < 24) {
            uint32_t boff = ((c + 1) & 1) * 40960;
            const char* sh = wh_base + (c + 1) * 64;
            const char* sl = wl_base + (c + 1) * 64;
#pragma unroll
            for (int q = 0; q < 4; q++) {
                cp16(bdst_h + boff + q * 16, sh + q * 16);
                cp16(bdst_l + boff + q * 16, sl + q * 16);
            }
            cp_commit();
            const float* xp = x + (rowBase + r_ld) * INF_ + (c + 1) * 32 + kh;
#pragma unroll
            for (int q = 0; q < 4; q++) rA[q] = *(const float4*)(xp + q * 4);
            cp_wait1();   // group c done (group c+1 may stay in flight)
        } else {
            cp_wait0();
        }
        __syncthreads();

        uint32_t uBh = usm + 20480 + (c & 1) * 40960;
        uint32_t uBl = uBh + 20480;
#pragma unroll
        for (int kb = 0; kb < 32; kb += 16) {
            uint32_t ah[4][4], al[4][4];
            int ak = kb + akg;
            int bk = kb + bkg;
#pragma unroll
            for (int fm = 0; fm < 4; fm++) {
                uint32_t off = ((warp_m * 64 + fm * 16 + ar) * SAPAD + ak) * 2;
                ldsm4(ah[fm], uAhi + off);
                ldsm4(al[fm], uAlo + off);
            }
#pragma unroll
            for (int p = 0; p < 4; p++) {      // fn pair p covers fn=2p, 2p+1
                uint32_t off = ((warp_n * 64 + p * 16 + br) * SAPAD + bk) * 2;
                uint32_t th[4], tl[4];
                ldsm4(th, uBh + off);
                ldsm4(tl, uBl + off);
#pragma unroll
                for (int fm = 0; fm < 4; fm++) {
                    mma_bf16(acc[fm][2 * p],     ah[fm], th);
                    mma_bf16(acc[fm][2 * p],     ah[fm], tl);
                    mma_bf16(acc[fm][2 * p],     al[fm], th);
                    mma_bf16(acc[fm][2 * p + 1], ah[fm], th + 2);
                    mma_bf16(acc[fm][2 * p + 1], ah[fm], tl + 2);
                    mma_bf16(acc[fm][2 * p + 1], al[fm], th + 2);
                }
            }
        }
    }

    // ---- epilogue: cols 0-127 -> g_h1, 128-255 -> g_proj ----
#pragma unroll
    for (int fm = 0; fm < 4; fm++) {
        long long r0 = rowBase + warp_m * 64 + fm * 16 + (lane >> 2);
        long long r1 = r0 + 8;
#pragma unroll
        for (int fn = 0; fn < 8; fn++) {
            int col = warp_n * 64 + fn * 8 + (lane & 3) * 2;
            float* C = (col < 128) ? (g_h1 + col) : (g_proj + (col - 128));
            C[r0 * HIDF]     = acc[fm][fn][0];
            C[r0 * HIDF + 1] = acc[fm][fn][1];
            C[r1 * HIDF]     = acc[fm][fn][2];
            C[r1 * HIDF + 1] = acc[fm][fn][3];
        }
    }
}

// ---------------- edge dtype probe ------------------------------------------
__device__ __forceinline__ int edge_at(const void* ei, int is64, long long idx) {
    if (is64) return (int)((const long long*)ei)[idx];
    return ((const int*)ei)[idx];
}
__global__ void k_probe(const int* __restrict__ ei32) {
    if (threadIdx.x == 0 && blockIdx.x == 0) {
        int is64 = 1;
        for (int i = 1; i < 128; i += 2)
            if (ei32[i] != 0) { is64 = 0; break; }
        g_is64 = is64;
    }
}

// ---------------- CSR build --------------------------------------------------
__global__ void k_init_deg() {
    int i = blockIdx.x * blockDim.x + threadIdx.x;
    if (i < NN) g_deg[i] = 1;   // self loop
}
__global__ void k_count(const void* __restrict__ ei, int E) {
    int i = blockIdx.x * blockDim.x + threadIdx.x;
    if (i < E) {
        int dst = edge_at(ei, g_is64, (long long)E + i);
        if ((unsigned)dst < NN) atomicAdd(&g_deg[dst], 1);
    }
}
// multi-block scan: A) per-block local scan, B) scan of 64 block sums, C) add-back
__global__ void k_scanA() {    // grid 64, block 256; thread owns 4 nodes
    __shared__ int ss[256];
    int b = blockIdx.x, t = threadIdx.x;
    int base = b * 1024 + t * 4;
    int4 d = *(const int4*)(g_deg + base);
    int tsum = d.x + d.y + d.z + d.w;
    ss[t] = tsum;
    __syncthreads();
    for (int off = 1; off < 256; off <<= 1) {
        int v = 0;
        if (t >= off) v = ss[t - off];
        __syncthreads();
        if (t >= off) ss[t] += v;
        __syncthreads();
    }
    int ex = ss[t] - tsum;
    g_off[base]     = ex;
    g_off[base + 1] = ex + d.x;
    g_off[base + 2] = ex + d.x + d.y;
    g_off[base + 3] = ex + d.x + d.y + d.z;
    if (t == 255) g_bsum[b] = ss[255];
}
__global__ void k_scanB() {    // 1 block, 64 threads
    __shared__ int ss[64];
    int t = threadIdx.x;
    int v = g_bsum[t];
    ss[t] = v;
    __syncthreads();
    for (int off = 1; off < 64; off <<= 1) {
        int u = 0;
        if (t >= off) u = ss[t - off];
        __syncthreads();
        if (t >= off) ss[t] += u;
        __syncthreads();
    }
    g_boff[t] = ss[t] - v;
    if (t == 63) g_off[NN] = ss[63];
}
__global__ void k_scanC() {    // grid 64, block 256
    int b = blockIdx.x, t = threadIdx.x;
    int add = g_boff[b];
    int i = b * 1024 + t * 4;
    int4 v = *(const int4*)(g_off + i);
    v.x += add; v.y += add; v.z += add; v.w += add;
    *(int4*)(g_off + i) = v;
    *(int4*)(g_cur + i) = v;
}
__global__ void k_scatter(const void* __restrict__ ei, int E, int N) {
    int i = blockIdx.x * blockDim.x + threadIdx.x;
    int total = E + N;
    if (i >= total) return;
    int src, dst;
    if (i < E) {
        src = edge_at(ei, g_is64, i);
        dst = edge_at(ei, g_is64, (long long)E + i);
    } else {
        src = i - E; dst = src;
    }
    if ((unsigned)dst >= (unsigned)N || (unsigned)src >= (unsigned)N) return;
    int pos = atomicAdd(&g_cur[dst], 1);
    if ((unsigned)pos < (unsigned)ET) g_csr[pos] = src;
}

// ---------------- per-node attention coefficients (layer 1) ------------------
__global__ void k_att1(const float* __restrict__ att_src, const float* __restrict__ att_dst) {
    __shared__ __align__(16) float s_s[HEADS * C1];
    __shared__ __align__(16) float s_d[HEADS * C1];
    int t = threadIdx.x;
    if (t < HEADS * C1) { s_s[t] = att_src[t]; s_d[t] = att_dst[t]; }
    __syncthreads();
    int idx = blockIdx.x * blockDim.x + t;
    if (idx >= NN * HEADS) return;
    int n = idx >> 3, h = idx & 7;
    const float* hp = g_h1 + (size_t)n * HIDF + h * C1;
    float as = 0.f, ad = 0.f;
#pragma unroll
    for (int c = 0; c < C1; c++) {
        float v = hp[c];
        as += v * s_s[h * C1 + c];
        ad += v * s_d[h * C1 + c];
    }
    g_as1[idx] = as;
    g_ad1[idx] = ad;
}

// ---------------- layer-1 aggregation: warp per destination ------------------
__device__ __forceinline__ float leaky(float v) { return v > 0.f ? v : NEG_SLOPE * v; }

__global__ void k_agg1(const float* __restrict__ b1, const float* __restrict__ bp) {
    int warp = blockIdx.x * 8 + (threadIdx.x >> 5);
    int lane = threadIdx.x & 31;
    if (warp >= NN) return;
    int n = warp;
    int beg = g_off[n], end = g_off[n + 1];

    float adn[HEADS];
#pragma unroll
    for (int h = 0; h < HEADS; h++) adn[h] = g_ad1[n * HEADS + h];

    // single online pass: per-head (max, scaled-sum)
    float m[HEADS], s[HEADS];
#pragma unroll
    for (int h = 0; h < HEADS; h++) { m[h] = -1e30f; s[h] = 0.f; }
    for (int e = beg + lane; e < end; e += 32) {
        int src = g_csr[e];
#pragma unroll
        for (int h = 0; h < HEADS; h++) {
            float eh = leaky(g_as1[src * HEADS + h] + adn[h]);
            float mn = fmaxf(m[h], eh);
            s[h] = s[h] * __expf(m[h] - mn) + __expf(eh - mn);
            m[h] = mn;
        }
    }
#pragma unroll
    for (int h = 0; h < HEADS; h++) {
#pragma unroll
        for (int o = 16; o > 0; o >>= 1) {
            float mo = __shfl_xor_sync(~0u, m[h], o);
            float so = __shfl_xor_sync(~0u, s[h], o);
            float mn = fmaxf(m[h], mo);
            s[h] = s[h] * __expf(m[h] - mn) + so * __expf(mo - mn);
            m[h] = mn;
        }
    }

    // select this lane's head values without dynamic register indexing
    int hd = lane >> 2;
    float m_h = m[0], s_h = s[0], ad_h = adn[0];
#pragma unroll
    for (int h = 1; h < HEADS; h++) {
        bool p = (hd == h);
        m_h  = p ? m[h]   : m_h;
        s_h  = p ? s[h]   : s_h;
        ad_h = p ? adn[h] : ad_h;
    }
    float inv_h = 1.f / (s_h + EPS);

    // weighted gather: lane owns 4 consecutive channels (head = lane/4)
    int cbase = lane * 4;
    float a0 = 0.f, a1 = 0.f, a2 = 0.f, a3 = 0.f;
    for (int e = beg; e < end; e++) {
        int src = g_csr[e];
        float w = __expf(leaky(g_as1[src * HEADS + hd] + ad_h) - m_h);
        const float* hp = g_h1 + (size_t)src * HIDF + cbase;
        a0 += hp[0] * w; a1 += hp[1] * w;
        a2 += hp[2] * w; a3 += hp[3] * w;
    }
    const float* pr = g_proj + (size_t)n * HIDF + cbase;
    float o0 = a0 * inv_h + b1[cbase + 0] + pr[0] + bp[cbase + 0];
    float o1 = a1 * inv_h + b1[cbase + 1] + pr[1] + bp[cbase + 1];
    float o2 = a2 * inv_h + b1[cbase + 2] + pr[2] + bp[cbase + 2];
    float o3 = a3 * inv_h + b1[cbase + 3] + pr[3] + bp[cbase + 3];
    o0 = o0 > 0.f ? o0 : expm1f(o0);
    o1 = o1 > 0.f ? o1 : expm1f(o1);
    o2 = o2 > 0.f ? o2 : expm1f(o2);
    o3 = o3 > 0.f ? o3 : expm1f(o3);
    float* op = g_hmid + (size_t)n * HIDF + cbase;
    op[0] = o0; op[1] = o1; op[2] = o2; op[3] = o3;
}

// ---------------- layer-2 projection + attention coefficients ----------------
__global__ void k_h2(
    const float* __restrict__ W2, const float* __restrict__ as2,
    const float* __restrict__ ad2)
{
    __shared__ __align__(16) float sW[HIDF * OUTF];
    __shared__ float sAtt[4];
    int t = threadIdx.x;
    if (t < HIDF * OUTF) sW[t] = W2[t];
    if (t < 2) { sAtt[t] = as2[t]; sAtt[2 + t] = ad2[t]; }
    __syncthreads();
    int warp = blockIdx.x * 8 + (t >> 5);
    int lane = t & 31;
    if (warp >= NN) return;
    int n = warp;
    const float* hp = g_hmid + (size_t)n * HIDF + lane * 4;
    float p0 = 0.f, p1 = 0.f;
#pragma unroll
    for (int j = 0; j < 4; j++) {
        float v = hp[j];
        p0 += v * sW[(lane * 4 + j) * 2 + 0];
        p1 += v * sW[(lane * 4 + j) * 2 + 1];
    }
#pragma unroll
    for (int o = 16; o > 0; o >>= 1) {
        p0 += __shfl_xor_sync(~0u, p0, o);
        p1 += __shfl_xor_sync(~0u, p1, o);
    }
    if (lane == 0) {
        g_h2[n * 2 + 0] = p0;
        g_h2[n * 2 + 1] = p1;
        g_as2[n] = p0 * sAtt[0] + p1 * sAtt[1];
        g_ad2[n] = p0 * sAtt[2] + p1 * sAtt[3];
    }
}

// ---------------- layer-2 aggregation: warp per destination ------------------
__global__ void k_agg2(const float* __restrict__ b2, float* __restrict__ out) {
    int warp = blockIdx.x * 8 + (threadIdx.x >> 5);
    int lane = threadIdx.x & 31;
    if (warp >= NN) return;
    int n = warp;
    int beg = g_off[n], end = g_off[n + 1];
    float adn = g_ad2[n];

    float mx = -1e30f;
    for (int e = beg + lane; e < end; e += 32)
        mx = fmaxf(mx, leaky(g_as2[g_csr[e]] + adn));
#pragma unroll
    for (int o = 16; o > 0; o >>= 1) mx = fmaxf(mx, __shfl_xor_sync(~0u, mx, o));

    float ssum = 0.f, a0 = 0.f, a1 = 0.f;
    for (int e = beg + lane; e < end; e += 32) {
        int src = g_csr[e];
        float w = __expf(leaky(g_as2[src] + adn) - mx);
        ssum += w;
        a0 += w * g_h2[src * 2 + 0];
        a1 += w * g_h2[src * 2 + 1];
    }
#pragma unroll
    for (int o = 16; o > 0; o >>= 1) {
        ssum += __shfl_xor_sync(~0u, ssum, o);
        a0 += __shfl_xor_sync(~0u, a0, o);
        a1 += __shfl_xor_sync(~0u, a1, o);
    }
    if (lane == 0) {
        float inv = 1.f / (ssum + EPS);
        out[n * 2 + 0] = a0 * inv + b2[0];
        out[n * 2 + 1] = a1 * inv + b2[1];
    }
}

// ---------------- launch -----------------------------------------------------
extern "C" void kernel_launch(void* const* d_in, const int* in_sizes, int n_in,
                              void* d_out, int out_size) {
    const float* x    = (const float*)d_in[0];
    const void*  ei   = d_in[1];                 // int32 or int64, probed on device
    const float* W1   = (const float*)d_in[2];
    const float* as1  = (const float*)d_in[3];
    const float* ad1  = (const float*)d_in[4];
    const float* b1   = (const float*)d_in[5];
    const float* Wp   = (const float*)d_in[6];
    const float* bp   = (const float*)d_in[7];
    const float* W2   = (const float*)d_in[8];
    const float* as2  = (const float*)d_in[9];
    const float* ad2  = (const float*)d_in[10];
    const float* b2   = (const float*)d_in[11];
    float* out = (float*)d_out;

    int N = in_sizes[0] / INF_;   // 65536
    int E = in_sizes[1] / 2;      // 1310720
    int ETOT = E + N;

    cudaFuncSetAttribute(k_gemm_mma, cudaFuncAttributeMaxDynamicSharedMemorySize, GEMM_SMEM);

    k_probe<<<1, 32>>>((const int*)ei);
    k_init_deg<<<(N + 255) / 256, 256>>>();
    k_count<<<(E + 255) / 256, 256>>>(ei, E);
    k_scanA<<<64, 256>>>();
    k_scanB<<<1, 64>>>();
    k_scanC<<<64, 256>>>();
    k_scatter<<<(ETOT + 255) / 256, 256>>>(ei, E, N);

    k_wprep<<<(256 * 768 + 255) / 256, 256>>>(W1, Wp);
    k_gemm_mma<<<N / 128, 256, GEMM_SMEM>>>(x);

    k_att1<<<(N * HEADS + 255) / 256, 256>>>(as1, ad1);
    k_agg1<<<N / 8, 256>>>(b1, bp);
    k_h2<<<N / 8, 256>>>(W2, as2, ad2);
    k_agg2<<<N / 8, 256>>>(b2, out);
}

// round 11
// speedup vs baseline: 1.1111x; 1.1111x over previous
#include <cuda_runtime.h>
#include <cuda_bf16.h>
#include <math.h>
#include <stdint.h>

// Problem constants (GAT_1090921693772)
#define NN 65536
#define EE 1310720
#define ET (NN + EE)          // edges + self loops
#define INF_ 768
#define HIDF 128
#define HEADS 8
#define C1 16
#define OUTF 2
#define NEG_SLOPE 0.2f
#define EPS 1e-16f

// ---------------- scratch (static device globals; no allocation) -------------
__device__ __align__(16) int   g_deg[NN];
__device__ __align__(16) int   g_off[NN + 1];
__device__ __align__(16) int   g_cur[NN];
__device__ __align__(16) int   g_csr[ET];
__device__ __align__(16) int   g_bsum[64];
__device__ __align__(16) int   g_boff[64];
__device__ __align__(16) float g_h1[(size_t)NN * HIDF];
__device__ __align__(16) float g_proj[(size_t)NN * HIDF];
__device__ __align__(16) float g_as1[NN * HEADS];
__device__ __align__(16) float g_ad1[NN * HEADS];
__device__ __align__(16) float g_hmid[(size_t)NN * HIDF];
__device__ __align__(16) float g_h2[NN * OUTF];
__device__ __align__(16) float g_as2[NN];
__device__ __align__(16) float g_ad2[NN];
__device__ int g_is64;   // 1 if edge_index is int64, 0 if int32

// bf16 hi/lo split of concatenated weights [256 n][768 k] (n<128 = W1, n>=128 = Wp)
__device__ __align__(16) __nv_bfloat16 g_wc_hi[256 * 768];
__device__ __align__(16) __nv_bfloat16 g_wc_lo[256 * 768];

// ---------------- PTX helpers (baseline ISA only — no tcgen05) ---------------
__device__ __forceinline__ uint32_t smem_u32(const void* p) {
    uint32_t a;
    asm("{ .reg .u64 t; cvta.to.shared.u64 t, %1; cvt.u32.u64 %0, t; }" : "=r"(a) : "l"(p));
    return a;
}
__device__ __forceinline__ void ldsm4(uint32_t* r, uint32_t addr) {
    asm volatile("ldmatrix.sync.aligned.m8n8.x4.shared.b16 {%0,%1,%2,%3}, [%4];"
                 : "=r"(r[0]), "=r"(r[1]), "=r"(r[2]), "=r"(r[3]) : "r"(addr));
}
__device__ __forceinline__ void mma_bf16(float* c, const uint32_t* a, const uint32_t* b) {
    asm volatile(
        "mma.sync.aligned.m16n8k16.row.col.f32.bf16.bf16.f32 "
        "{%0,%1,%2,%3}, {%4,%5,%6,%7}, {%8,%9}, {%0,%1,%2,%3};"
        : "+f"(c[0]), "+f"(c[1]), "+f"(c[2]), "+f"(c[3])
        : "r"(a[0]), "r"(a[1]), "r"(a[2]), "r"(a[3]), "r"(b[0]), "r"(b[1]));
}

// ---------------- weight prep: split W1||Wp into bf16 hi/lo [256][768] -------
__global__ void k_wprep(const float* __restrict__ W1, const float* __restrict__ Wp) {
    int idx = blockIdx.x * 256 + threadIdx.x;
    if (idx >= 256 * 768) return;
    int n = idx / 768, k = idx % 768;
    float v = (n < 128) ? W1[k * HIDF + n] : Wp[k * HIDF + (n - 128)];
    __nv_bfloat16 hi = __float2bfloat16(v);
    float lo = v - __bfloat162float(hi);
    g_wc_hi[idx] = hi;
    g_wc_lo[idx] = __float2bfloat16(lo);
}

// ---------------- tensor-core GEMM via mma.sync (bf16 3-product split) -------
// grid (512 row-tiles, 2 col-tiles). CTA tile 128x128, 8 warps of 64x32, BK=32.
#define SAPAD 40   // bf16 row stride: 80B = 16B-aligned, conflict-free ldmatrix
__global__ __launch_bounds__(256) void k_gemm_mma(const float* __restrict__ x) {
    __shared__ __align__(16) __nv_bfloat16 sAhi[128 * SAPAD];
    __shared__ __align__(16) __nv_bfloat16 sAlo[128 * SAPAD];
    __shared__ __align__(16) __nv_bfloat16 sBhi[128 * SAPAD];
    __shared__ __align__(16) __nv_bfloat16 sBlo[128 * SAPAD];

    int tid = threadIdx.x;
    int wid = tid >> 5, lane = tid & 31;
    int warp_m = wid >> 2, warp_n = wid & 3;     // 2 x 4 warp grid
    long long rowBase = (long long)blockIdx.x * 128;
    const __nv_bfloat16* Wh = g_wc_hi + (size_t)blockIdx.y * 128 * INF_;
    const __nv_bfloat16* Wl = g_wc_lo + (size_t)blockIdx.y * 128 * INF_;

    uint32_t uAhi = smem_u32(sAhi), uAlo = smem_u32(sAlo);
    uint32_t uBhi = smem_u32(sBhi), uBlo = smem_u32(sBlo);

    float acc[4][4][4];
#pragma unroll
    for (int i = 0; i < 4; i++)
#pragma unroll
        for (int j = 0; j < 4; j++)
#pragma unroll
            for (int q = 0; q < 4; q++) acc[i][j][q] = 0.f;

    // ldmatrix lane addressing
    int ar = (lane & 7) + ((lane >> 3) & 1) * 8;
    int akg = ((lane >> 4) & 1) * 8;
    int br = (lane & 7) + ((lane >> 4) & 1) * 8;
    int bkg = ((lane >> 3) & 1) * 8;

    int r_ld = tid >> 1;                 // row/n this thread loads
    int kh = (tid & 1) * 16;             // k-half

    for (int kt = 0; kt < INF_; kt += 32) {
        __syncthreads();   // previous iteration's reads complete before overwrite
        // ---- A: 128x32 fp32 -> bf16 hi/lo ----
        {
            const float* xp = x + (rowBase + r_ld) * INF_ + kt + kh;
            __nv_bfloat16* dh = sAhi + r_ld * SAPAD + kh;
            __nv_bfloat16* dl = sAlo + r_ld * SAPAD + kh;
#pragma unroll
            for (int q = 0; q < 4; q++) {
                float4 v = *(const float4*)(xp + q * 4);
                __nv_bfloat16 h0 = __float2bfloat16(v.x);
                __nv_bfloat16 h1 = __float2bfloat16(v.y);
                __nv_bfloat16 h2 = __float2bfloat16(v.z);
                __nv_bfloat16 h3 = __float2bfloat16(v.w);
                __nv_bfloat162 ph0; ph0.x = h0; ph0.y = h1;
                __nv_bfloat162 ph1; ph1.x = h2; ph1.y = h3;
                __nv_bfloat162 pl0 = __floats2bfloat162_rn(v.x - __bfloat162float(h0),
                                                           v.y - __bfloat162float(h1));
                __nv_bfloat162 pl1 = __floats2bfloat162_rn(v.z - __bfloat162float(h2),
                                                           v.w - __bfloat162float(h3));
                *(__nv_bfloat162*)(dh + q * 4)     = ph0;
                *(__nv_bfloat162*)(dh + q * 4 + 2) = ph1;
                *(__nv_bfloat162*)(dl + q * 4)     = pl0;
                *(__nv_bfloat162*)(dl + q * 4 + 2) = pl1;
            }
        }
        // ---- B: 128x32 bf16 hi/lo, vector copy ----
        {
            const __nv_bfloat16* wh = Wh + (size_t)r_ld * INF_ + kt + kh;
            const __nv_bfloat16* wl = Wl + (size_t)r_ld * INF_ + kt + kh;
            *(uint4*)(sBhi + r_ld * SAPAD + kh)     = *(const uint4*)wh;
            *(uint4*)(sBhi + r_ld * SAPAD + kh + 8) = *(const uint4*)(wh + 8);
            *(uint4*)(sBlo + r_ld * SAPAD + kh)     = *(const uint4*)wl;
            *(uint4*)(sBlo + r_ld * SAPAD + kh + 8) = *(const uint4*)(wl + 8);
        }
        __syncthreads();

#pragma unroll
        for (int kb = 0; kb < 32; kb += 16) {
            uint32_t ah[4][4], al[4][4], bh[4][2], bl[4][2];
            int ak = kb + akg;
            int bk = kb + bkg;
#pragma unroll
            for (int fm = 0; fm < 4; fm++) {
                uint32_t off = ((warp_m * 64 + fm * 16 + ar) * SAPAD + ak) * 2;
                ldsm4(ah[fm], uAhi + off);
                ldsm4(al[fm], uAlo + off);
            }
#pragma unroll
            for (int p = 0; p < 2; p++) {      // fn pair p covers fn=2p, 2p+1
                uint32_t off = ((warp_n * 32 + p * 16 + br) * SAPAD + bk) * 2;
                uint32_t t[4];
                ldsm4(t, uBhi + off);
                bh[2 * p][0] = t[0]; bh[2 * p][1] = t[1];
                bh[2 * p + 1][0] = t[2]; bh[2 * p + 1][1] = t[3];
                ldsm4(t, uBlo + off);
                bl[2 * p][0] = t[0]; bl[2 * p][1] = t[1];
                bl[2 * p + 1][0] = t[2]; bl[2 * p + 1][1] = t[3];
            }
#pragma unroll
            for (int fm = 0; fm < 4; fm++)
#pragma unroll
                for (int fn = 0; fn < 4; fn++) {
                    mma_bf16(acc[fm][fn], ah[fm], bh[fn]);
                    mma_bf16(acc[fm][fn], ah[fm], bl[fn]);
                    mma_bf16(acc[fm][fn], al[fm], bh[fn]);
                }
        }
    }

    // ---- epilogue ----
    float* C = (blockIdx.y == 0) ? g_h1 : g_proj;
#pragma unroll
    for (int fm = 0; fm < 4; fm++) {
        long long r0 = rowBase + warp_m * 64 + fm * 16 + (lane >> 2);
        long long r1 = r0 + 8;
#pragma unroll
        for (int fn = 0; fn < 4; fn++) {
            int col = warp_n * 32 + fn * 8 + (lane & 3) * 2;
            C[r0 * HIDF + col]     = acc[fm][fn][0];
            C[r0 * HIDF + col + 1] = acc[fm][fn][1];
            C[r1 * HIDF + col]     = acc[fm][fn][2];
            C[r1 * HIDF + col + 1] = acc[fm][fn][3];
        }
    }
}

// ---------------- edge dtype probe ------------------------------------------
__device__ __forceinline__ int edge_at(const void* ei, int is64, long long idx) {
    if (is64) return (int)((const long long*)ei)[idx];
    return ((const int*)ei)[idx];
}
__global__ void k_probe(const int* __restrict__ ei32) {
    if (threadIdx.x == 0 && blockIdx.x == 0) {
        int is64 = 1;
        for (int i = 1; i < 128; i += 2)
            if (ei32[i] != 0) { is64 = 0; break; }
        g_is64 = is64;
    }
}

// ---------------- CSR build --------------------------------------------------
__global__ void k_init_deg() {
    int i = blockIdx.x * blockDim.x + threadIdx.x;
    if (i < NN) g_deg[i] = 1;   // self loop
}
__global__ void k_count(const void* __restrict__ ei, int E) {
    int i = blockIdx.x * blockDim.x + threadIdx.x;
    if (i < E) {
        int dst = edge_at(ei, g_is64, (long long)E + i);
        if ((unsigned)dst < NN) atomicAdd(&g_deg[dst], 1);
    }
}
// multi-block scan: A) per-block local scan, B) scan of 64 block sums, C) add-back
__global__ void k_scanA() {    // grid 64, block 256; thread owns 4 nodes
    __shared__ int ss[256];
    int b = blockIdx.x, t = threadIdx.x;
    int base = b * 1024 + t * 4;
    int4 d = *(const int4*)(g_deg + base);
    int tsum = d.x + d.y + d.z + d.w;
    ss[t] = tsum;
    __syncthreads();
    for (int off = 1; off < 256; off <<= 1) {
        int v = 0;
        if (t >= off) v = ss[t - off];
        __syncthreads();
        if (t >= off) ss[t] += v;
        __syncthreads();
    }
    int ex = ss[t] - tsum;
    g_off[base]     = ex;
    g_off[base + 1] = ex + d.x;
    g_off[base + 2] = ex + d.x + d.y;
    g_off[base + 3] = ex + d.x + d.y + d.z;
    if (t == 255) g_bsum[b] = ss[255];
}
__global__ void k_scanB() {    // 1 block, 64 threads
    __shared__ int ss[64];
    int t = threadIdx.x;
    int v = g_bsum[t];
    ss[t] = v;
    __syncthreads();
    for (int off = 1; off < 64; off <<= 1) {
        int u = 0;
        if (t >= off) u = ss[t - off];
        __syncthreads();
        if (t >= off) ss[t] += u;
        __syncthreads();
    }
    g_boff[t] = ss[t] - v;
    if (t == 63) g_off[NN] = ss[63];
}
__global__ void k_scanC() {    // grid 64, block 256
    int b = blockIdx.x, t = threadIdx.x;
    int add = g_boff[b];
    int i = b * 1024 + t * 4;
    int4 v = *(const int4*)(g_off + i);
    v.x += add; v.y += add; v.z += add; v.w += add;
    *(int4*)(g_off + i) = v;
    *(int4*)(g_cur + i) = v;
}
__global__ void k_scatter(const void* __restrict__ ei, int E, int N) {
    int i = blockIdx.x * blockDim.x + threadIdx.x;
    int total = E + N;
    if (i >= total) return;
    int src, dst;
    if (i < E) {
        src = edge_at(ei, g_is64, i);
        dst = edge_at(ei, g_is64, (long long)E + i);
    } else {
        src = i - E; dst = src;
    }
    if ((unsigned)dst >= (unsigned)N || (unsigned)src >= (unsigned)N) return;
    int pos = atomicAdd(&g_cur[dst], 1);
    if ((unsigned)pos < (unsigned)ET) g_csr[pos] = src;
}

// ---------------- per-node attention coefficients (layer 1) ------------------
__global__ void k_att1(const float* __restrict__ att_src, const float* __restrict__ att_dst) {
    __shared__ __align__(16) float s_s[HEADS * C1];
    __shared__ __align__(16) float s_d[HEADS * C1];
    int t = threadIdx.x;
    if (t < HEADS * C1) { s_s[t] = att_src[t]; s_d[t] = att_dst[t]; }
    __syncthreads();
    int idx = blockIdx.x * blockDim.x + t;
    if (idx >= NN * HEADS) return;
    int n = idx >> 3, h = idx & 7;
    const float* hp = g_h1 + (size_t)n * HIDF + h * C1;
    float as = 0.f, ad = 0.f;
#pragma unroll
    for (int c = 0; c < C1; c++) {
        float v = hp[c];
        as += v * s_s[h * C1 + c];
        ad += v * s_d[h * C1 + c];
    }
    g_as1[idx] = as;
    g_ad1[idx] = ad;
}

// ---------------- layer-1 aggregation: warp per destination ------------------
__device__ __forceinline__ float leaky(float v) { return v > 0.f ? v : NEG_SLOPE * v; }

__global__ void k_agg1(const float* __restrict__ b1, const float* __restrict__ bp) {
    int warp = blockIdx.x * 8 + (threadIdx.x >> 5);
    int lane = threadIdx.x & 31;
    if (warp >= NN) return;
    int n = warp;
    int beg = g_off[n], end = g_off[n + 1];

    float adn[HEADS];
#pragma unroll
    for (int h = 0; h < HEADS; h++) adn[h] = g_ad1[n * HEADS + h];

    float m[HEADS];
#pragma unroll
    for (int h = 0; h < HEADS; h++) m[h] = -1e30f;
    for (int e = beg + lane; e < end; e += 32) {
        int src = g_csr[e];
#pragma unroll
        for (int h = 0; h < HEADS; h++)
            m[h] = fmaxf(m[h], leaky(g_as1[src * HEADS + h] + adn[h]));
    }
#pragma unroll
    for (int h = 0; h < HEADS; h++)
#pragma unroll
        for (int o = 16; o > 0; o >>= 1) m[h] = fmaxf(m[h], __shfl_xor_sync(~0u, m[h], o));

    float s[HEADS];
#pragma unroll
    for (int h = 0; h < HEADS; h++) s[h] = 0.f;
    for (int e = beg + lane; e < end; e += 32) {
        int src = g_csr[e];
#pragma unroll
        for (int h = 0; h < HEADS; h++)
            s[h] += __expf(leaky(g_as1[src * HEADS + h] + adn[h]) - m[h]);
    }
#pragma unroll
    for (int h = 0; h < HEADS; h++)
#pragma unroll
        for (int o = 16; o > 0; o >>= 1) s[h] += __shfl_xor_sync(~0u, s[h], o);

    int hd = lane >> 2;
    float m_h = m[0], s_h = s[0], ad_h = adn[0];
#pragma unroll
    for (int h = 1; h < HEADS; h++) {
        bool p = (hd == h);
        m_h  = p ? m[h]   : m_h;
        s_h  = p ? s[h]   : s_h;
        ad_h = p ? adn[h] : ad_h;
    }
    float inv_h = 1.f / (s_h + EPS);

    int cbase = lane * 4;
    float a0 = 0.f, a1 = 0.f, a2 = 0.f, a3 = 0.f;
    for (int e = beg; e < end; e++) {
        int src = g_csr[e];
        float w = __expf(leaky(g_as1[src * HEADS + hd] + ad_h) - m_h);
        const float* hp = g_h1 + (size_t)src * HIDF + cbase;
        a0 += hp[0] * w; a1 += hp[1] * w;
        a2 += hp[2] * w; a3 += hp[3] * w;
    }
    const float* pr = g_proj + (size_t)n * HIDF + cbase;
    float o0 = a0 * inv_h + b1[cbase + 0] + pr[0] + bp[cbase + 0];
    float o1 = a1 * inv_h + b1[cbase + 1] + pr[1] + bp[cbase + 1];
    float o2 = a2 * inv_h + b1[cbase + 2] + pr[2] + bp[cbase + 2];
    float o3 = a3 * inv_h + b1[cbase + 3] + pr[3] + bp[cbase + 3];
    o0 = o0 > 0.f ? o0 : expm1f(o0);
    o1 = o1 > 0.f ? o1 : expm1f(o1);
    o2 = o2 > 0.f ? o2 : expm1f(o2);
    o3 = o3 > 0.f ? o3 : expm1f(o3);
    float* op = g_hmid + (size_t)n * HIDF + cbase;
    op[0] = o0; op[1] = o1; op[2] = o2; op[3] = o3;
}

// ---------------- layer-2 projection + attention coefficients ----------------
__global__ void k_h2(
    const float* __restrict__ W2, const float* __restrict__ as2,
    const float* __restrict__ ad2)
{
    __shared__ __align__(16) float sW[HIDF * OUTF];
    __shared__ float sAtt[4];
    int t = threadIdx.x;
    if (t < HIDF * OUTF) sW[t] = W2[t];
    if (t < 2) { sAtt[t] = as2[t]; sAtt[2 + t] = ad2[t]; }
    __syncthreads();
    int warp = blockIdx.x * 8 + (t >> 5);
    int lane = t & 31;
    if (warp >= NN) return;
    int n = warp;
    const float* hp = g_hmid + (size_t)n * HIDF + lane * 4;
    float p0 = 0.f, p1 = 0.f;
#pragma unroll
    for (int j = 0; j < 4; j++) {
        float v = hp[j];
        p0 += v * sW[(lane * 4 + j) * 2 + 0];
        p1 += v * sW[(lane * 4 + j) * 2 + 1];
    }
#pragma unroll
    for (int o = 16; o > 0; o >>= 1) {
        p0 += __shfl_xor_sync(~0u, p0, o);
        p1 += __shfl_xor_sync(~0u, p1, o);
    }
    if (lane == 0) {
        g_h2[n * 2 + 0] = p0;
        g_h2[n * 2 + 1] = p1;
        g_as2[n] = p0 * sAtt[0] + p1 * sAtt[1];
        g_ad2[n] = p0 * sAtt[2] + p1 * sAtt[3];
    }
}

// ---------------- layer-2 aggregation: warp per destination ------------------
__global__ void k_agg2(const float* __restrict__ b2, float* __restrict__ out) {
    int warp = blockIdx.x * 8 + (threadIdx.x >> 5);
    int lane = threadIdx.x & 31;
    if (warp >= NN) return;
    int n = warp;
    int beg = g_off[n], end = g_off[n + 1];
    float adn = g_ad2[n];

    float mx = -1e30f;
    for (int e = beg + lane; e < end; e += 32)
        mx = fmaxf(mx, leaky(g_as2[g_csr[e]] + adn));
#pragma unroll
    for (int o = 16; o > 0; o >>= 1) mx = fmaxf(mx, __shfl_xor_sync(~0u, mx, o));

    float ssum = 0.f, a0 = 0.f, a1 = 0.f;
    for (int e = beg + lane; e < end; e += 32) {
        int src = g_csr[e];
        float w = __expf(leaky(g_as2[src] + adn) - mx);
        ssum += w;
        a0 += w * g_h2[src * 2 + 0];
        a1 += w * g_h2[src * 2 + 1];
    }
#pragma unroll
    for (int o = 16; o > 0; o >>= 1) {
        ssum += __shfl_xor_sync(~0u, ssum, o);
        a0 += __shfl_xor_sync(~0u, a0, o);
        a1 += __shfl_xor_sync(~0u, a1, o);
    }
    if (lane == 0) {
        float inv = 1.f / (ssum + EPS);
        out[n * 2 + 0] = a0 * inv + b2[0];
        out[n * 2 + 1] = a1 * inv + b2[1];
    }
}

// ---------------- launch -----------------------------------------------------
extern "C" void kernel_launch(void* const* d_in, const int* in_sizes, int n_in,
                              void* d_out, int out_size) {
    const float* x    = (const float*)d_in[0];
    const void*  ei   = d_in[1];                 // int32 or int64, probed on device
    const float* W1   = (const float*)d_in[2];
    const float* as1  = (const float*)d_in[3];
    const float* ad1  = (const float*)d_in[4];
    const float* b1   = (const float*)d_in[5];
    const float* Wp   = (const float*)d_in[6];
    const float* bp   = (const float*)d_in[7];
    const float* W2   = (const float*)d_in[8];
    const float* as2  = (const float*)d_in[9];
    const float* ad2  = (const float*)d_in[10];
    const float* b2   = (const float*)d_in[11];
    float* out = (float*)d_out;

    int N = in_sizes[0] / INF_;   // 65536
    int E = in_sizes[1] / 2;      // 1310720
    int ETOT = E + N;

    k_probe<<<1, 32>>>((const int*)ei);
    k_init_deg<<<(N + 255) / 256, 256>>>();
    k_count<<<(E + 255) / 256, 256>>>(ei, E);
    k_scanA<<<64, 256>>>();
    k_scanB<<<1, 64>>>();
    k_scanC<<<64, 256>>>();
    k_scatter<<<(ETOT + 255) / 256, 256>>>(ei, E, N);

    k_wprep<<<(256 * 768 + 255) / 256, 256>>>(W1, Wp);
    dim3 ggrid(N / 128, 2);
    k_gemm_mma<<<ggrid, 256>>>(x);

    k_att1<<<(N * HEADS + 255) / 256, 256>>>(as1, ad1);
    k_agg1<<<N / 8, 256>>>(b1, bp);
    k_h2<<<N / 8, 256>>>(W2, as2, ad2);
    k_agg2<<<N / 8, 256>>>(b2, out);
}